// round 2
// baseline (speedup 1.0000x reference)
#include <cuda_runtime.h>
#include <math.h>

#define BATCH 512
#define LATENT 128

// ---------------- scratch (static device arrays; no runtime allocs) ----------
__device__ float g_lp[BATCH * 32];                 //   64 KB
__device__ float g_b0[BATCH * 128 * 8 * 8];        // 16.8 MB  [n][128][8][8]
__device__ float g_b1[BATCH * 128 * 16 * 16];      // 67 MB    [n][128][16][16]
__device__ float g_b2[BATCH * 64 * 32 * 32];       // 134 MB   [n][64][32][32]

// ---------------- stage 1: gating + soft-tree leaf probabilities -------------
// grid = BATCH blocks, 32 threads (1 warp). Lane j<31 computes gate j,
// then lane l computes leaf prob l as product of 5 gate terms.
__global__ void leaf_kernel(const float* __restrict__ x,
                            const float* __restrict__ gw,
                            const float* __restrict__ gb,
                            float* __restrict__ lp) {
    int b = blockIdx.x;
    int lane = threadIdx.x;
    __shared__ float xs[LATENT];
    __shared__ float gs[32];
    for (int k = lane; k < LATENT; k += 32) xs[k] = x[b * LATENT + k];
    __syncthreads();
    if (lane < 31) {
        float acc = gb[lane];
#pragma unroll 8
        for (int k = 0; k < LATENT; k++) acc += xs[k] * gw[k * 31 + lane];
        gs[lane] = 1.0f / (1.0f + expf(-acc));
    }
    __syncthreads();
    // leaf index l: bit at depth d = (l >> (5-d)) & 1 (0 = left = g, 1 = right = 1-g)
    // parent index at depth d = l >> (6-d); gate = (2^(d-1)-1) + parent
    float dens = 1.0f;
    int l = lane;
#pragma unroll
    for (int d = 1; d <= 5; d++) {
        int par  = l >> (6 - d);
        int gate = (1 << (d - 1)) - 1 + par;
        int bit  = (l >> (5 - d)) & 1;
        float gv = gs[gate];
        dens *= bit ? (1.0f - gv) : gv;
    }
    lp[b * 32 + l] = dens;
}

// ---------------- stage 2: out0[b][f] = sum_l lp[b][l] * z[f][l] -------------
// Each thread owns one f (32 z-values in registers, float4 loads) and loops
// 8 batch rows => z traffic reduced 8x. grid = (8192/256, 512/8), block 256.
__global__ void mix_kernel(const float* __restrict__ lp,
                           const float* __restrict__ z,
                           float* __restrict__ out0) {
    __shared__ float lps[8][32];
    int tid = threadIdx.x;
    int f = blockIdx.x * 256 + tid;
    int b0 = blockIdx.y * 8;
    lps[tid >> 5][tid & 31] = lp[b0 * 32 + tid];   // 256 = 8 rows x 32
    __syncthreads();
    float4 zr[8];
    const float4* zp = (const float4*)(z + (size_t)f * 32);
#pragma unroll
    for (int j = 0; j < 8; j++) zr[j] = zp[j];
#pragma unroll
    for (int bb = 0; bb < 8; bb++) {
        const float* lr = lps[bb];
        float acc = 0.0f;
#pragma unroll
        for (int j = 0; j < 8; j++) {
            float4 zv = zr[j];
            acc += zv.x * lr[4 * j] + zv.y * lr[4 * j + 1]
                 + zv.z * lr[4 * j + 2] + zv.w * lr[4 * j + 3];
        }
        out0[(size_t)(b0 + bb) * 8192 + f] = acc;
    }
}

// ---------------- stage 3/4/5: ConvTranspose2d(k=4, s=2, p=1) ----------------
// Split into 4 parity classes (py, px). Output (oy=2q+py, ox=2r+px) reads input
// rows {q+py-1, q+py} with ky = 3-py-2*ra and cols {r+px-1, r+px} with
// kx = 3-px-2*rb  (exactly a 2x2 gather conv per class).
// Each thread: U output channels x T=4 consecutive class-columns.
// Shared: ICB input channels of the image + per-class reordered weights.
template <int CIN, int HIN, int COUT, int U, int T, int ICB, bool RELU>
__global__ void convt_kernel(const float* __restrict__ in,
                             const float* __restrict__ w,
                             const float* __restrict__ bias,
                             float* __restrict__ out) {
    constexpr int HOUT    = 2 * HIN;
    constexpr int NPIX    = HIN * HIN;
    constexpr int GPR     = HIN / T;           // pixel groups per class row
    constexpr int PGROUPS = NPIX / T;
    constexpr int OGROUPS = COUT / U;
    constexpr int THREADS = PGROUPS * OGROUPS;

    extern __shared__ float sm[];
    float* xs = sm;                  // [ICB][HIN][HIN]
    float* ws = sm + ICB * NPIX;     // [ICB][COUT][4]  (4 = ra*2+rb for this class)

    const int n   = blockIdx.x;
    const int cls = blockIdx.y;
    const int py = cls >> 1, px = cls & 1;
    const int tid = threadIdx.x;
    const int p  = tid % PGROUPS;
    const int u0 = (tid / PGROUPS) * U;
    const int q  = p / GPR;
    const int r0 = (p % GPR) * T;

    const int row_base = q + py - 1;
    const int col_base = r0 + px - 1;
    bool rowok[2];
    int  rowix[2];
    rowok[0] = (row_base >= 0);       rowix[0] = rowok[0] ? row_base : 0;
    rowok[1] = (row_base + 1 < HIN);  rowix[1] = rowok[1] ? row_base + 1 : 0;
    bool colok[T + 1];
    int  colix[T + 1];
#pragma unroll
    for (int c = 0; c <= T; c++) {
        int cc = col_base + c;
        colok[c] = (cc >= 0 && cc < HIN);
        colix[c] = colok[c] ? cc : 0;
    }

    float acc[U][T];
#pragma unroll
    for (int uu = 0; uu < U; uu++)
#pragma unroll
        for (int t = 0; t < T; t++) acc[uu][t] = 0.0f;

    const float* inb = in + (size_t)n * CIN * NPIX;

    for (int ic0 = 0; ic0 < CIN; ic0 += ICB) {
        __syncthreads();
        // stage input chunk (contiguous, coalesced)
        for (int idx = tid; idx < ICB * NPIX; idx += THREADS)
            xs[idx] = inb[(size_t)ic0 * NPIX + idx];
        // stage class weights, reordered to [i][oc][ra*2+rb]
        for (int idx = tid; idx < ICB * COUT * 4; idx += THREADS) {
            int i   = idx / (COUT * 4);
            int rem = idx - i * (COUT * 4);
            int oc  = rem >> 2;
            int t4  = rem & 3;
            int ra = t4 >> 1, rb = t4 & 1;
            int ky = 3 - py - 2 * ra;
            int kx = 3 - px - 2 * rb;
            ws[idx] = w[((size_t)(ic0 + i) * COUT + oc) * 16 + ky * 4 + kx];
        }
        __syncthreads();

        for (int i = 0; i < ICB; i++) {
            float xv[2][T + 1];
#pragma unroll
            for (int a = 0; a < 2; a++) {
                const float* xr = xs + (i * HIN + rowix[a]) * HIN;
#pragma unroll
                for (int c = 0; c <= T; c++) {
                    float v = xr[colix[c]];
                    xv[a][c] = (rowok[a] && colok[c]) ? v : 0.0f;
                }
            }
            const float* wsi = ws + (i * COUT + u0) * 4;
#pragma unroll
            for (int uu = 0; uu < U; uu++) {
                float w00 = wsi[uu * 4 + 0];
                float w01 = wsi[uu * 4 + 1];
                float w10 = wsi[uu * 4 + 2];
                float w11 = wsi[uu * 4 + 3];
#pragma unroll
                for (int t = 0; t < T; t++)
                    acc[uu][t] += xv[0][t] * w00 + xv[0][t + 1] * w01
                                + xv[1][t] * w10 + xv[1][t + 1] * w11;
            }
        }
    }

    const int oy = 2 * q + py;
    float* outb = out + (size_t)n * COUT * HOUT * HOUT;
#pragma unroll
    for (int uu = 0; uu < U; uu++) {
        int oc = u0 + uu;
        float bv = bias[oc];
        float* orow = outb + ((size_t)oc * HOUT + oy) * HOUT;
#pragma unroll
        for (int t = 0; t < T; t++) {
            int ox = 2 * (r0 + t) + px;
            float v = acc[uu][t] + bv;
            if (RELU) v = fmaxf(v, 0.0f);
            orow[ox] = v;
        }
    }
}

// ---------------- launch -----------------------------------------------------
extern "C" void kernel_launch(void* const* d_in, const int* in_sizes, int n_in,
                              void* d_out, int out_size) {
    const float* x  = (const float*)d_in[0];
    const float* gw = (const float*)d_in[1];
    const float* gb = (const float*)d_in[2];
    const float* z  = (const float*)d_in[3];
    const float* w1 = (const float*)d_in[4];
    const float* b1 = (const float*)d_in[5];
    const float* w2 = (const float*)d_in[6];
    const float* b2 = (const float*)d_in[7];
    const float* w3 = (const float*)d_in[8];
    const float* b3 = (const float*)d_in[9];
    float* out = (float*)d_out;

    float *lp, *bf0, *bf1, *bf2;
    cudaGetSymbolAddress((void**)&lp,  g_lp);
    cudaGetSymbolAddress((void**)&bf0, g_b0);
    cudaGetSymbolAddress((void**)&bf1, g_b1);
    cudaGetSymbolAddress((void**)&bf2, g_b2);

    leaf_kernel<<<BATCH, 32>>>(x, gw, gb, lp);
    mix_kernel<<<dim3(8192 / 256, BATCH / 8), 256>>>(lp, z, bf0);

    // conv1: 128 -> 128, 8x8 -> 16x16, ReLU.  256 threads, smem 36 KB
    convt_kernel<128, 8, 128, 8, 4, 16, true>
        <<<dim3(BATCH, 4), 256, (16 * 64 + 16 * 128 * 4) * sizeof(float)>>>(bf0, w1, b1, bf1);
    // conv2: 128 -> 64, 16x16 -> 32x32, ReLU. 512 threads, smem 32 KB
    convt_kernel<128, 16, 64, 8, 4, 16, true>
        <<<dim3(BATCH, 4), 512, (16 * 256 + 16 * 64 * 4) * sizeof(float)>>>(bf1, w2, b2, bf2);
    // conv3: 64 -> 3, 32x32 -> 64x64, no ReLU. 256 threads, smem ~33 KB
    convt_kernel<64, 32, 3, 3, 4, 8, false>
        <<<dim3(BATCH, 4), 256, (8 * 1024 + 8 * 3 * 4) * sizeof(float)>>>(bf2, w3, b3, out);
}